// round 14
// baseline (speedup 1.0000x reference)
#include <cuda_runtime.h>
#include <cuda_fp16.h>
#include <cstdint>

// Problem constants
#define BB_ 16
#define TT_ 8192
#define DD_ 192
#define KK_ 512
#define SPAN_ 8
#define BS_ 16384
#define NTOK_ (BB_*TT_)

// Output layout: q_out | loss | idx_out | boundaries (float32)
#define Q_ELEMS (BB_*TT_*DD_)
#define LOSS_OFF (Q_ELEMS)
#define IDX_OFF  (Q_ELEMS + 1)
#define BND_OFF  (IDX_OFF + NTOK_)

// K2: CTA = 128 segs x 512 codes; 8 chunks of 64 codes; 256 threads = 8 warps
// (4 M-groups x 2 N-groups), warp = 2 m-tiles x 4 n-tiles.
// fp16 double-split: value = v1 + v2s/2048.
#define TM2_ 128
#define NC_ 64
#define NCHUNK2_ 8
#define NTHR2_ 256
#define KS16_ 12
#define A_U4 6144
#define A_BYTES (A_U4*16)                 // 98304
#define B_CHUNK_U4 (8*KS16_*32)           // 3072 uint4 = 48KB
#define K2_DYN (A_BYTES + 2*B_CHUNK_U4*16)  // 196608
#define INV2048_ (1.0f/2048.0f)
#define GRID2_ (BS_/TM2_)                 // 128
#define GRID1_ (NTOK_/256)                // 512
#define GRID3_ (BS_/4)                    // 4096

// Scratch (__device__ globals; no allocation allowed)
__device__ __align__(16) float g_pooled[BS_*DD_];
__device__ uint4 g_pA4[BS_*DD_/4];
__device__ uint4 g_cbF4[64*KS16_*32];
__device__ float g_hnorm[KK_];
__device__ int   g_sidx[BS_];
__device__ double g_eblk[GRID3_];
__device__ int   g_bcnt[GRID1_];
__device__ int   g_done;                  // zero-init; self-resets each replay

// ---------------------------------------------------------------------------
// helpers (sm_100 base-target safe)
// ---------------------------------------------------------------------------
__device__ __forceinline__ uint32_t smem_u32(const void* p) {
    uint32_t a;
    asm("{ .reg .u64 t; cvta.to.shared.u64 t, %1; cvt.u32.u64 %0, t; }"
        : "=r"(a) : "l"(p));
    return a;
}
__device__ __forceinline__ void cp16(uint32_t dst, const void* src) {
    asm volatile("cp.async.cg.shared.global [%0], [%1], 16;"
                 :: "r"(dst), "l"(src) : "memory");
}
__device__ __forceinline__ void cp_commit() {
    asm volatile("cp.async.commit_group;" ::: "memory");
}
__device__ __forceinline__ void cp_wait1() {
    asm volatile("cp.async.wait_group 1;" ::: "memory");
}
__device__ __forceinline__ void cp_wait0() {
    asm volatile("cp.async.wait_group 0;" ::: "memory");
}
__device__ __forceinline__ uint32_t packh2(float lo, float hi) {
    __half2 h = __halves2half2(__float2half_rn(lo), __float2half_rn(hi));
    return *(uint32_t*)&h;
}
__device__ __forceinline__ float h1f(float v) {
    return __half2float(__float2half_rn(v));
}
__device__ __forceinline__ float h2sf(float v) {
    return (v - h1f(v)) * 2048.0f;
}
__device__ __forceinline__ void mma16(float* c, const uint32_t* a,
                                      uint32_t b0, uint32_t b1) {
    asm volatile(
        "mma.sync.aligned.m16n8k16.row.col.f32.f16.f16.f32 "
        "{%0,%1,%2,%3}, {%4,%5,%6,%7}, {%8,%9}, {%0,%1,%2,%3};"
        : "+f"(c[0]), "+f"(c[1]), "+f"(c[2]), "+f"(c[3])
        : "r"(a[0]), "r"(a[1]), "r"(a[2]), "r"(a[3]), "r"(b0), "r"(b1));
}

// ---------------------------------------------------------------------------
// K1: boundary predictor + segment pooling + pA fragments (R10 core),
// with codebook prep (B fragments + half norms) FUSED into blocks 0..95.
// ---------------------------------------------------------------------------
__global__ void __launch_bounds__(256) k1_pool_boundary(
    const float* __restrict__ x,
    const float* __restrict__ cb,
    const float* __restrict__ bw,
    const float* __restrict__ bb,
    float* __restrict__ bnd_out)
{
    __shared__ float sx[256 * 33];
    __shared__ float pTc[32 * 33];
    __shared__ float s_bw[DD_];
    __shared__ int   s_cnt;
    const int tid = threadIdx.x;
    const long tok0 = (long)blockIdx.x * 256;
    const int s0 = blockIdx.x * 32;

    // ---- fused codebook prep (blocks 0..95) ----
    if (blockIdx.x < 96) {
        int i = blockIdx.x * 256 + tid;         // 24576 total
        int lane = i & 31;
        int ks = (i >> 5) % KS16_;
        int nt = i / (KS16_ * 32);              // 0..63
        int gid = lane >> 2, tig = lane & 3;
        const float* row = cb + (long)(nt * 8 + gid) * DD_ + ks * 16;
        float v0 = row[2 * tig], v1 = row[2 * tig + 1];
        float v2 = row[2 * tig + 8], v3 = row[2 * tig + 9];
        uint4 r;
        r.x = packh2(h1f(v0), h1f(v1));
        r.y = packh2(h1f(v2), h1f(v3));
        r.z = packh2(h2sf(v0), h2sf(v1));
        r.w = packh2(h2sf(v2), h2sf(v3));
        g_cbF4[(nt * KS16_ + ks) * 32 + lane] = r;
    }
    if (blockIdx.x < 64) {
        const int w = blockIdx.x * 8 + (tid >> 5);
        const int lane = tid & 31;
        float s = 0.f;
        #pragma unroll
        for (int j = 0; j < 6; j++) {
            float v = cb[(long)w * DD_ + lane + 32 * j];
            s += v * v;
        }
        #pragma unroll
        for (int m = 16; m > 0; m >>= 1) s += __shfl_xor_sync(0xffffffffu, s, m);
        if (lane == 0) g_hnorm[w] = 0.5f * s;
    }

    if (tid < DD_) s_bw[tid] = bw[tid];
    if (tid == 0) s_cnt = 0;

    float logit = 0.f;

    #pragma unroll 1
    for (int dc = 0; dc < 6; dc++) {
        for (int i = tid; i < 2048; i += 256) {
            int token = i >> 3, j4 = (i & 7) * 4;
            float4 v = *(const float4*)(x + (tok0 + token) * DD_ + dc * 32 + j4);
            float* p = &sx[token * 33 + j4];
            p[0] = v.x; p[1] = v.y; p[2] = v.z; p[3] = v.w;
        }
        __syncthreads();

        {
            const float* row = &sx[tid * 33];
            const float* bwc = &s_bw[dc * 32];
            float l = 0.f;
            #pragma unroll 8
            for (int j = 0; j < 32; j++) l += row[j] * bwc[j];
            logit += l;
        }

        // pooled: 32 segs x 32 d, 4 outputs per thread
        #pragma unroll
        for (int m = 0; m < 4; m++) {
            int o = tid + 256 * m;
            int seg = o >> 5, d = o & 31;
            float s = 0.f;
            #pragma unroll
            for (int t = 0; t < SPAN_; t++) s += sx[(seg * 8 + t) * 33 + d];
            s *= 0.125f;
            g_pooled[(long)(s0 + seg) * DD_ + dc * 32 + d] = s;
            pTc[seg * 33 + d] = s;
        }
        __syncthreads();

        // A-fragment pass: dc chunk = 2 k16 slabs x 2 m-tiles x {a1,a2s}
        {
            const int lane = tid & 31;
            const int q = tid >> 5;
            const int s16 = q >> 2;
            const int mt = (q >> 1) & 1;
            const int which = q & 1;
            const int gid = lane >> 2, tig = lane & 3;
            const int r0 = mt * 16 + gid, r1 = r0 + 8;
            const int c0 = s16 * 16 + 2 * tig;
            float v00 = pTc[r0 * 33 + c0],     v01 = pTc[r0 * 33 + c0 + 1];
            float v02 = pTc[r0 * 33 + c0 + 8], v03 = pTc[r0 * 33 + c0 + 9];
            float v10 = pTc[r1 * 33 + c0],     v11 = pTc[r1 * 33 + c0 + 1];
            float v12 = pTc[r1 * 33 + c0 + 8], v13 = pTc[r1 * 33 + c0 + 9];
            uint4 r;
            if (which == 0) {
                r.x = packh2(h1f(v00), h1f(v01));
                r.y = packh2(h1f(v10), h1f(v11));
                r.z = packh2(h1f(v02), h1f(v03));
                r.w = packh2(h1f(v12), h1f(v13));
            } else {
                r.x = packh2(h2sf(v00), h2sf(v01));
                r.y = packh2(h2sf(v10), h2sf(v11));
                r.z = packh2(h2sf(v02), h2sf(v03));
                r.w = packh2(h2sf(v12), h2sf(v13));
            }
            int mt_g = blockIdx.x * 2 + mt;
            int b2 = mt_g >> 3;
            int wy8 = mt_g & 7;
            int ks = dc * 2 + s16;
            g_pA4[(long)b2 * A_U4 + ((wy8 * KS16_ + ks) * 2 + which) * 32 + lane] = r;
        }
        __syncthreads();
    }

    float lg = logit + bb[0];
    float flag = (lg > 0.f) ? 1.f : 0.f;
    bnd_out[tok0 + tid] = flag;
    unsigned m = __ballot_sync(0xffffffffu, flag > 0.f);
    if ((tid & 31) == 0) atomicAdd(&s_cnt, __popc(m));
    __syncthreads();
    if (tid == 0) g_bcnt[blockIdx.x] = s_cnt;
}

// ---------------------------------------------------------------------------
// K2: double-fp16 VQ search via mma.sync.m16n8k16 (R10, unchanged).
// ---------------------------------------------------------------------------
extern __shared__ __align__(1024) char k2smem[];

__global__ void __launch_bounds__(NTHR2_, 1) k2_vq()
{
    __shared__ float s_hn[KK_];
    __shared__ float s_bv[2][TM2_];
    __shared__ int   s_bi[2][TM2_];

    const int tid = threadIdx.x;
    const int wid = tid >> 5, lane = tid & 31;
    const int wy = wid >> 1, wx = wid & 1;
    const int gid = lane >> 2, tig = lane & 3;
    const int s0 = blockIdx.x * TM2_;

    uint4* smA = (uint4*)k2smem;
    uint4* smB = (uint4*)(k2smem + A_BYTES);
    const uint32_t smA_u = smem_u32(smA);
    const uint32_t smB_u = smem_u32(smB);

    {
        const uint4* srcA = g_pA4 + (long)blockIdx.x * A_U4;
        for (int i = tid; i < A_U4; i += NTHR2_)
            cp16(smA_u + (uint32_t)i * 16, srcA + i);
        for (int i = tid; i < B_CHUNK_U4; i += NTHR2_)
            cp16(smB_u + (uint32_t)i * 16, g_cbF4 + i);
        cp_commit();
        for (int i = tid; i < B_CHUNK_U4; i += NTHR2_)
            cp16(smB_u + (uint32_t)(B_CHUNK_U4 + i) * 16, g_cbF4 + B_CHUNK_U4 + i);
        cp_commit();
    }
    for (int i = tid; i < KK_; i += NTHR2_) s_hn[i] = g_hnorm[i];

    float best[4]; int bidx[4];
    #pragma unroll
    for (int i = 0; i < 4; i++) { best[i] = -3.0e38f; bidx[i] = 0; }

    float acc_h[2][4][4], acc_l1[2][4][4], acc_l2[2][4][4];
    #pragma unroll
    for (int mt = 0; mt < 2; mt++)
        #pragma unroll
        for (int ni = 0; ni < 4; ni++)
            #pragma unroll
            for (int j = 0; j < 4; j++) {
                acc_h[mt][ni][j] = 0.f;
                acc_l1[mt][ni][j] = 0.f;
                acc_l2[mt][ni][j] = 0.f;
            }

    const uint4* aPtr0 = smA + (wy * 2 + 0) * (KS16_ * 2 * 32) + lane;
    const uint4* aPtr1 = smA + (wy * 2 + 1) * (KS16_ * 2 * 32) + lane;

    for (int ch = 0; ch < NCHUNK2_; ch++) {
        if (ch < NCHUNK2_ - 1) cp_wait1(); else cp_wait0();
        __syncthreads();

        const uint4* bufB = smB + (ch & 1) * B_CHUNK_U4;
        const uint4* bPtr = bufB + (wx * 4) * (KS16_ * 32) + lane;

        #pragma unroll 2
        for (int ks = 0; ks < KS16_; ks++) {
            uint4 a10 = aPtr0[ks * 64];
            uint4 a20 = aPtr0[ks * 64 + 32];
            uint4 a11 = aPtr1[ks * 64];
            uint4 a21 = aPtr1[ks * 64 + 32];
            const uint32_t* a1m0 = (const uint32_t*)&a10;
            const uint32_t* a2m0 = (const uint32_t*)&a20;
            const uint32_t* a1m1 = (const uint32_t*)&a11;
            const uint32_t* a2m1 = (const uint32_t*)&a21;
            #pragma unroll
            for (int ni = 0; ni < 4; ni++) {
                uint4 b = bPtr[ni * (KS16_ * 32) + ks * 32];
                mma16(acc_h [0][ni], a1m0, b.x, b.y);
                mma16(acc_l1[0][ni], a1m0, b.z, b.w);
                mma16(acc_l2[0][ni], a2m0, b.x, b.y);
                mma16(acc_h [1][ni], a1m1, b.x, b.y);
                mma16(acc_l1[1][ni], a1m1, b.z, b.w);
                mma16(acc_l2[1][ni], a2m1, b.x, b.y);
            }
        }
        __syncthreads();

        if (ch < NCHUNK2_ - 2) {
            const uint4* src = g_cbF4 + (long)(ch + 2) * B_CHUNK_U4;
            uint32_t dst = smB_u + (uint32_t)((ch & 1) * B_CHUNK_U4) * 16;
            for (int i = tid; i < B_CHUNK_U4; i += NTHR2_)
                cp16(dst + (uint32_t)i * 16, src + i);
            cp_commit();
        }

        #pragma unroll
        for (int ni = 0; ni < 4; ni++) {
            const int codeb = ch * NC_ + (wx * 4 + ni) * 8 + 2 * tig;
            const float hn0 = s_hn[codeb], hn1 = s_hn[codeb + 1];
            #pragma unroll
            for (int mt = 0; mt < 2; mt++) {
                #pragma unroll
                for (int j = 0; j < 4; j++) {
                    float sc = acc_h[mt][ni][j]
                             + (acc_l1[mt][ni][j] + acc_l2[mt][ni][j]) * INV2048_
                             - ((j & 1) ? hn1 : hn0);
                    int slot = mt * 2 + (j >> 1);
                    int code = codeb + (j & 1);
                    if (sc > best[slot]) { best[slot] = sc; bidx[slot] = code; }
                    acc_h[mt][ni][j] = 0.f;
                    acc_l1[mt][ni][j] = 0.f;
                    acc_l2[mt][ni][j] = 0.f;
                }
            }
        }
    }

    #pragma unroll
    for (int slot = 0; slot < 4; slot++) {
        float b = best[slot]; int ix = bidx[slot];
        #pragma unroll
        for (int m = 1; m <= 2; m <<= 1) {
            float ob = __shfl_xor_sync(0xffffffffu, b, m);
            int   oi = __shfl_xor_sync(0xffffffffu, ix, m);
            if (ob > b || (ob == b && oi < ix)) { b = ob; ix = oi; }
        }
        if (tig == 0) {
            int segl = wy * 32 + (slot >> 1) * 16 + gid + 8 * (slot & 1);
            s_bv[wx][segl] = b;
            s_bi[wx][segl] = ix;
        }
    }
    __syncthreads();

    if (tid < TM2_) {
        float b0 = s_bv[0][tid], b1 = s_bv[1][tid];
        int   i0 = s_bi[0][tid], i1 = s_bi[1][tid];
        int take1 = (b1 > b0) || (b1 == b0 && i1 < i0);
        g_sidx[s0 + tid] = take1 ? i1 : i0;
    }
}

// ---------------------------------------------------------------------------
// K3: gather + STE broadcast + idx_out + per-block e partial, with the loss
// finalization fused via last-CTA ticket. Reduction FIXED: fold 192->64,
// then a power-of-two tree (the 96..3->1 halving chain dropped sd[2]).
// ---------------------------------------------------------------------------
__global__ void __launch_bounds__(192) k3_expand(
    const float* __restrict__ cb, float* __restrict__ out)
{
    __shared__ float se[192];
    __shared__ double sd[192];
    __shared__ int s_ticket;
    const int tid = threadIdx.x;
    const int sl = tid / 48, slot = tid - sl * 48;
    const int s = blockIdx.x * 4 + sl;
    const int idx = g_sidx[s];
    float4 c4 = *(const float4*)(cb + (long)idx * DD_ + slot * 4);
    float4 p4 = *(const float4*)(g_pooled + (long)s * DD_ + slot * 4);
    float4 q4;
    q4.x = p4.x + (c4.x - p4.x);
    q4.y = p4.y + (c4.y - p4.y);
    q4.z = p4.z + (c4.z - p4.z);
    q4.w = p4.w + (c4.w - p4.w);
    float dx = c4.x - p4.x, dy = c4.y - p4.y, dz = c4.z - p4.z, dw = c4.w - p4.w;
    se[tid] = dx * dx + dy * dy + dz * dz + dw * dw;
    __syncthreads();
    if (tid == 0) {
        double t = 0.0;
        #pragma unroll 4
        for (int j = 0; j < 192; j++) t += (double)se[j];
        g_eblk[blockIdx.x] = t;
        __threadfence();
        s_ticket = atomicAdd(&g_done, 1);
    }
    float4* qb = (float4*)out + (long)s * 384 + slot;
    #pragma unroll
    for (int tk = 0; tk < SPAN_; tk++) qb[tk * 48] = q4;
    if (slot < SPAN_) out[IDX_OFF + s * SPAN_ + slot] = (float)idx;

    __syncthreads();
    if (s_ticket == GRID3_ - 1) {
        // last CTA: deterministic loss finalize
        __threadfence();
        double e = 0.0;
        for (int i = tid; i < GRID3_; i += 192) e += g_eblk[i];
        int bc = 0;
        for (int i = tid; i < GRID1_; i += 192) bc += g_bcnt[i];
        sd[tid] = e;
        se[tid] = (float)bc;   // exact: counts <= 131072 < 2^24
        __syncthreads();
        // fold 192 -> 64, then clean power-of-two tree
        if (tid < 64) {
            sd[tid] += sd[tid + 64] + sd[tid + 128];
            se[tid] += se[tid + 64] + se[tid + 128];
        }
        __syncthreads();
        for (int st = 32; st > 0; st >>= 1) {
            if (tid < st) { sd[tid] += sd[tid + st]; se[tid] += se[tid + st]; }
            __syncthreads();
        }
        if (tid == 0) {
            float e_mean = (float)(sd[0] / (double)((long)BS_ * DD_));
            float bm = se[0] / (float)NTOK_;
            float dbm = bm - (1.0f / SPAN_);
            out[LOSS_OFF] = 0.25f * e_mean + 0.01f * dbm * dbm;
            g_done = 0;       // reset for the next graph replay
        }
    }
}

// ---------------------------------------------------------------------------
extern "C" void kernel_launch(void* const* d_in, const int* in_sizes, int n_in,
                              void* d_out, int out_size)
{
    const float* x  = (const float*)d_in[0];
    const float* cb = (const float*)d_in[1];
    const float* bw = (const float*)d_in[2];
    const float* bb = (const float*)d_in[3];
    float* out = (float*)d_out;
    (void)in_sizes; (void)n_in; (void)out_size;

    cudaFuncSetAttribute(k2_vq, cudaFuncAttributeMaxDynamicSharedMemorySize,
                         K2_DYN);

    k1_pool_boundary<<<GRID1_, 256>>>(x, cb, bw, bb, out + BND_OFF);
    k2_vq<<<GRID2_, NTHR2_, K2_DYN>>>();
    k3_expand<<<GRID3_, 192>>>(cb, out);
}

// round 15
// speedup vs baseline: 1.1354x; 1.1354x over previous
#include <cuda_runtime.h>
#include <cuda_fp16.h>
#include <cstdint>

// Problem constants
#define BB_ 16
#define TT_ 8192
#define DD_ 192
#define KK_ 512
#define SPAN_ 8
#define BS_ 16384
#define NTOK_ (BB_*TT_)

// Output layout: q_out | loss | idx_out | boundaries (float32)
#define Q_ELEMS (BB_*TT_*DD_)
#define LOSS_OFF (Q_ELEMS)
#define IDX_OFF  (Q_ELEMS + 1)
#define BND_OFF  (IDX_OFF + NTOK_)

// K2: CTA = 128 segs x 512 codes; 8 chunks of 64 codes; 256 threads = 8 warps
// (4 M-groups x 2 N-groups), warp = 2 m-tiles x 4 n-tiles.
// fp16 double-split: value = v1 + v2s/2048.
#define TM2_ 128
#define NC_ 64
#define NCHUNK2_ 8
#define NTHR2_ 256
#define KS16_ 12
#define A_U4 6144
#define A_BYTES (A_U4*16)                 // 98304
#define B_CHUNK_U4 (8*KS16_*32)           // 3072 uint4 = 48KB
#define K2_DYN (A_BYTES + 2*B_CHUNK_U4*16)  // 196608
#define INV2048_ (1.0f/2048.0f)
#define GRID2_ (BS_/TM2_)                 // 128
#define PSTR_ 193                         // pTc row stride (odd -> conflict-free cols)

// Scratch (__device__ globals; no allocation allowed)
__device__ __align__(16) float g_pooled[BS_*DD_];
__device__ uint4 g_pA4[BS_*DD_/4];
__device__ uint4 g_cbF4[64*KS16_*32];
__device__ float g_hnorm[KK_];
__device__ int   g_sidx[BS_];
__device__ float g_epart[BS_];
__device__ int   g_bcount;

// ---------------------------------------------------------------------------
// helpers (sm_100 base-target safe)
// ---------------------------------------------------------------------------
__device__ __forceinline__ uint32_t smem_u32(const void* p) {
    uint32_t a;
    asm("{ .reg .u64 t; cvta.to.shared.u64 t, %1; cvt.u32.u64 %0, t; }"
        : "=r"(a) : "l"(p));
    return a;
}
__device__ __forceinline__ void cp16(uint32_t dst, const void* src) {
    asm volatile("cp.async.cg.shared.global [%0], [%1], 16;"
                 :: "r"(dst), "l"(src) : "memory");
}
__device__ __forceinline__ void cp_commit() {
    asm volatile("cp.async.commit_group;" ::: "memory");
}
__device__ __forceinline__ void cp_wait1() {
    asm volatile("cp.async.wait_group 1;" ::: "memory");
}
__device__ __forceinline__ void cp_wait0() {
    asm volatile("cp.async.wait_group 0;" ::: "memory");
}
__device__ __forceinline__ uint32_t packh2(float lo, float hi) {
    __half2 h = __halves2half2(__float2half_rn(lo), __float2half_rn(hi));
    return *(uint32_t*)&h;
}
__device__ __forceinline__ float h1f(float v) {
    return __half2float(__float2half_rn(v));
}
__device__ __forceinline__ float h2sf(float v) {
    return (v - h1f(v)) * 2048.0f;
}
__device__ __forceinline__ void mma16(float* c, const uint32_t* a,
                                      uint32_t b0, uint32_t b1) {
    asm volatile(
        "mma.sync.aligned.m16n8k16.row.col.f32.f16.f16.f32 "
        "{%0,%1,%2,%3}, {%4,%5,%6,%7}, {%8,%9}, {%0,%1,%2,%3};"
        : "+f"(c[0]), "+f"(c[1]), "+f"(c[2]), "+f"(c[3])
        : "r"(a[0]), "r"(a[1]), "r"(a[2]), "r"(a[3]), "r"(b0), "r"(b1));
}

// ---------------------------------------------------------------------------
// Kprep: codebook -> B-fragment order (double-fp16 split) + half norms +
// boundary-counter zero (R10, unchanged).
// ---------------------------------------------------------------------------
__global__ void __launch_bounds__(256) k_prep(const float* __restrict__ cb)
{
    int i = blockIdx.x * 256 + threadIdx.x;     // 24576 total
    if (blockIdx.x == 0 && threadIdx.x == 0) g_bcount = 0;
    {
        int lane = i & 31;
        int ks = (i >> 5) % KS16_;
        int nt = i / (KS16_ * 32);              // 0..63
        int gid = lane >> 2, tig = lane & 3;
        const float* row = cb + (long)(nt * 8 + gid) * DD_ + ks * 16;
        float v0 = row[2 * tig], v1 = row[2 * tig + 1];
        float v2 = row[2 * tig + 8], v3 = row[2 * tig + 9];
        uint4 r;
        r.x = packh2(h1f(v0), h1f(v1));
        r.y = packh2(h1f(v2), h1f(v3));
        r.z = packh2(h2sf(v0), h2sf(v1));
        r.w = packh2(h2sf(v2), h2sf(v3));
        g_cbF4[(nt * KS16_ + ks) * 32 + lane] = r;
    }
    if (blockIdx.x < 64) {
        const int w = blockIdx.x * 8 + (threadIdx.x >> 5);
        const int lane = threadIdx.x & 31;
        float s = 0.f;
        #pragma unroll
        for (int j = 0; j < 6; j++) {
            float v = cb[(long)w * DD_ + lane + 32 * j];
            s += v * v;
        }
        #pragma unroll
        for (int m = 16; m > 0; m >>= 1) s += __shfl_xor_sync(0xffffffffu, s, m);
        if (lane == 0) g_hnorm[w] = 0.5f * s;
    }
}

// ---------------------------------------------------------------------------
// K1 (REWRITTEN): barrier-free warp-per-segment pooling + boundary logits.
// 8 warps x 4 seg-iterations = 32 segments/block; x read straight into
// registers (8 coalesced 128B loads per d-chunk), pooled sequentially
// (t=0..7, reference order), logits held in 8 per-lane partials reduced by
// shuffles. ONE __syncthreads before the pA-fragment pass (R10 code over
// all 6 chunks, reading the pTc staging block).
// ---------------------------------------------------------------------------
__global__ void __launch_bounds__(256) k1_pool_boundary(
    const float* __restrict__ x,
    const float* __restrict__ bw,
    const float* __restrict__ bb,
    float* __restrict__ bnd_out)
{
    __shared__ float pTc[32 * PSTR_];   // pooled block [32 segs][192 d]
    __shared__ int   s_cnt;
    const int tid = threadIdx.x;
    const int w = tid >> 5, lane = tid & 31;
    const int s0 = blockIdx.x * 32;

    if (tid == 0) s_cnt = 0;

    // bw held in registers: 6 values per lane
    float bwr[6];
    #pragma unroll
    for (int dc = 0; dc < 6; dc++) bwr[dc] = __ldg(&bw[dc * 32 + lane]);
    const float bb0 = __ldg(&bb[0]);

    #pragma unroll 1
    for (int i = 0; i < 4; i++) {
        const int seg = w + 8 * i;              // local segment 0..31
        const float* xb = x + ((long)(s0 + seg) * SPAN_) * DD_;
        float lp[8];
        #pragma unroll
        for (int t = 0; t < 8; t++) lp[t] = 0.f;

        #pragma unroll
        for (int dc = 0; dc < 6; dc++) {
            float v[8];
            #pragma unroll
            for (int t = 0; t < 8; t++)
                v[t] = xb[t * DD_ + dc * 32 + lane];
            float pool = v[0];
            #pragma unroll
            for (int t = 1; t < 8; t++) pool += v[t];
            pool *= 0.125f;
            g_pooled[(long)(s0 + seg) * DD_ + dc * 32 + lane] = pool;
            pTc[seg * PSTR_ + dc * 32 + lane] = pool;
            #pragma unroll
            for (int t = 0; t < 8; t++) lp[t] += v[t] * bwr[dc];
        }

        // per-token logit reduction: lane t ends holding token t's sum
        float mylg = 0.f;
        #pragma unroll
        for (int t = 0; t < 8; t++) {
            float l = lp[t];
            #pragma unroll
            for (int m = 16; m > 0; m >>= 1)
                l += __shfl_xor_sync(0xffffffffu, l, m);
            if (lane == t) mylg = l;
        }
        float flag = (mylg + bb0 > 0.f) ? 1.f : 0.f;
        if (lane < 8)
            bnd_out[(long)(s0 + seg) * SPAN_ + lane] = flag;
        unsigned msk = __ballot_sync(0xffffffffu, (lane < 8) && (flag > 0.f));
        if (lane == 0) atomicAdd(&s_cnt, __popc(msk));
    }
    __syncthreads();

    // pA-fragment pass (R10 mapping, looped over the 6 d-chunks)
    #pragma unroll 1
    for (int dc = 0; dc < 6; dc++) {
        const int q = tid >> 5;             // 0..7
        const int s16 = q >> 2;             // k16 slab within chunk
        const int mt = (q >> 1) & 1;        // m-tile within block
        const int which = q & 1;            // 0 = a1, 1 = a2s
        const int gid = lane >> 2, tig = lane & 3;
        const int r0 = mt * 16 + gid, r1 = r0 + 8;
        const int c0 = dc * 32 + s16 * 16 + 2 * tig;
        float v00 = pTc[r0 * PSTR_ + c0],     v01 = pTc[r0 * PSTR_ + c0 + 1];
        float v02 = pTc[r0 * PSTR_ + c0 + 8], v03 = pTc[r0 * PSTR_ + c0 + 9];
        float v10 = pTc[r1 * PSTR_ + c0],     v11 = pTc[r1 * PSTR_ + c0 + 1];
        float v12 = pTc[r1 * PSTR_ + c0 + 8], v13 = pTc[r1 * PSTR_ + c0 + 9];
        uint4 r;
        if (which == 0) {
            r.x = packh2(h1f(v00), h1f(v01));
            r.y = packh2(h1f(v10), h1f(v11));
            r.z = packh2(h1f(v02), h1f(v03));
            r.w = packh2(h1f(v12), h1f(v13));
        } else {
            r.x = packh2(h2sf(v00), h2sf(v01));
            r.y = packh2(h2sf(v10), h2sf(v11));
            r.z = packh2(h2sf(v02), h2sf(v03));
            r.w = packh2(h2sf(v12), h2sf(v13));
        }
        int mt_g = blockIdx.x * 2 + mt;
        int b2 = mt_g >> 3;
        int wy8 = mt_g & 7;
        int ks = dc * 2 + s16;
        g_pA4[(long)b2 * A_U4 + ((wy8 * KS16_ + ks) * 2 + which) * 32 + lane] = r;
    }

    if (tid == 0) atomicAdd(&g_bcount, s_cnt);
}

// ---------------------------------------------------------------------------
// K2: double-fp16 VQ search via mma.sync.m16n8k16 (R10, unchanged).
// ---------------------------------------------------------------------------
extern __shared__ __align__(1024) char k2smem[];

__global__ void __launch_bounds__(NTHR2_, 1) k2_vq()
{
    __shared__ float s_hn[KK_];
    __shared__ float s_bv[2][TM2_];
    __shared__ int   s_bi[2][TM2_];

    const int tid = threadIdx.x;
    const int wid = tid >> 5, lane = tid & 31;
    const int wy = wid >> 1, wx = wid & 1;
    const int gid = lane >> 2, tig = lane & 3;
    const int s0 = blockIdx.x * TM2_;

    uint4* smA = (uint4*)k2smem;
    uint4* smB = (uint4*)(k2smem + A_BYTES);
    const uint32_t smA_u = smem_u32(smA);
    const uint32_t smB_u = smem_u32(smB);

    {
        const uint4* srcA = g_pA4 + (long)blockIdx.x * A_U4;
        for (int i = tid; i < A_U4; i += NTHR2_)
            cp16(smA_u + (uint32_t)i * 16, srcA + i);
        for (int i = tid; i < B_CHUNK_U4; i += NTHR2_)
            cp16(smB_u + (uint32_t)i * 16, g_cbF4 + i);
        cp_commit();
        for (int i = tid; i < B_CHUNK_U4; i += NTHR2_)
            cp16(smB_u + (uint32_t)(B_CHUNK_U4 + i) * 16, g_cbF4 + B_CHUNK_U4 + i);
        cp_commit();
    }
    for (int i = tid; i < KK_; i += NTHR2_) s_hn[i] = g_hnorm[i];

    float best[4]; int bidx[4];
    #pragma unroll
    for (int i = 0; i < 4; i++) { best[i] = -3.0e38f; bidx[i] = 0; }

    float acc_h[2][4][4], acc_l1[2][4][4], acc_l2[2][4][4];
    #pragma unroll
    for (int mt = 0; mt < 2; mt++)
        #pragma unroll
        for (int ni = 0; ni < 4; ni++)
            #pragma unroll
            for (int j = 0; j < 4; j++) {
                acc_h[mt][ni][j] = 0.f;
                acc_l1[mt][ni][j] = 0.f;
                acc_l2[mt][ni][j] = 0.f;
            }

    const uint4* aPtr0 = smA + (wy * 2 + 0) * (KS16_ * 2 * 32) + lane;
    const uint4* aPtr1 = smA + (wy * 2 + 1) * (KS16_ * 2 * 32) + lane;

    for (int ch = 0; ch < NCHUNK2_; ch++) {
        if (ch < NCHUNK2_ - 1) cp_wait1(); else cp_wait0();
        __syncthreads();

        const uint4* bufB = smB + (ch & 1) * B_CHUNK_U4;
        const uint4* bPtr = bufB + (wx * 4) * (KS16_ * 32) + lane;

        #pragma unroll 2
        for (int ks = 0; ks < KS16_; ks++) {
            uint4 a10 = aPtr0[ks * 64];
            uint4 a20 = aPtr0[ks * 64 + 32];
            uint4 a11 = aPtr1[ks * 64];
            uint4 a21 = aPtr1[ks * 64 + 32];
            const uint32_t* a1m0 = (const uint32_t*)&a10;
            const uint32_t* a2m0 = (const uint32_t*)&a20;
            const uint32_t* a1m1 = (const uint32_t*)&a11;
            const uint32_t* a2m1 = (const uint32_t*)&a21;
            #pragma unroll
            for (int ni = 0; ni < 4; ni++) {
                uint4 b = bPtr[ni * (KS16_ * 32) + ks * 32];
                mma16(acc_h [0][ni], a1m0, b.x, b.y);
                mma16(acc_l1[0][ni], a1m0, b.z, b.w);
                mma16(acc_l2[0][ni], a2m0, b.x, b.y);
                mma16(acc_h [1][ni], a1m1, b.x, b.y);
                mma16(acc_l1[1][ni], a1m1, b.z, b.w);
                mma16(acc_l2[1][ni], a2m1, b.x, b.y);
            }
        }
        __syncthreads();

        if (ch < NCHUNK2_ - 2) {
            const uint4* src = g_cbF4 + (long)(ch + 2) * B_CHUNK_U4;
            uint32_t dst = smB_u + (uint32_t)((ch & 1) * B_CHUNK_U4) * 16;
            for (int i = tid; i < B_CHUNK_U4; i += NTHR2_)
                cp16(dst + (uint32_t)i * 16, src + i);
            cp_commit();
        }

        #pragma unroll
        for (int ni = 0; ni < 4; ni++) {
            const int codeb = ch * NC_ + (wx * 4 + ni) * 8 + 2 * tig;
            const float hn0 = s_hn[codeb], hn1 = s_hn[codeb + 1];
            #pragma unroll
            for (int mt = 0; mt < 2; mt++) {
                #pragma unroll
                for (int j = 0; j < 4; j++) {
                    float sc = acc_h[mt][ni][j]
                             + (acc_l1[mt][ni][j] + acc_l2[mt][ni][j]) * INV2048_
                             - ((j & 1) ? hn1 : hn0);
                    int slot = mt * 2 + (j >> 1);
                    int code = codeb + (j & 1);
                    if (sc > best[slot]) { best[slot] = sc; bidx[slot] = code; }
                    acc_h[mt][ni][j] = 0.f;
                    acc_l1[mt][ni][j] = 0.f;
                    acc_l2[mt][ni][j] = 0.f;
                }
            }
        }
    }

    #pragma unroll
    for (int slot = 0; slot < 4; slot++) {
        float b = best[slot]; int ix = bidx[slot];
        #pragma unroll
        for (int m = 1; m <= 2; m <<= 1) {
            float ob = __shfl_xor_sync(0xffffffffu, b, m);
            int   oi = __shfl_xor_sync(0xffffffffu, ix, m);
            if (ob > b || (ob == b && oi < ix)) { b = ob; ix = oi; }
        }
        if (tig == 0) {
            int segl = wy * 32 + (slot >> 1) * 16 + gid + 8 * (slot & 1);
            s_bv[wx][segl] = b;
            s_bi[wx][segl] = ix;
        }
    }
    __syncthreads();

    if (tid < TM2_) {
        float b0 = s_bv[0][tid], b1 = s_bv[1][tid];
        int   i0 = s_bi[0][tid], i1 = s_bi[1][tid];
        int take1 = (b1 > b0) || (b1 == b0 && i1 < i0);
        g_sidx[s0 + tid] = take1 ? i1 : i0;
    }
}

// ---------------------------------------------------------------------------
// K3: gather + STE broadcast (float4), per-segment e partial, idx_out
// (R10, unchanged).
// ---------------------------------------------------------------------------
__global__ void __launch_bounds__(192) k3_expand(
    const float* __restrict__ cb, float* __restrict__ out)
{
    __shared__ float se[192];
    const int tid = threadIdx.x;
    const int sl = tid / 48, slot = tid - sl * 48;
    const int s = blockIdx.x * 4 + sl;
    const int idx = g_sidx[s];
    float4 c4 = *(const float4*)(cb + (long)idx * DD_ + slot * 4);
    float4 p4 = *(const float4*)(g_pooled + (long)s * DD_ + slot * 4);
    float4 q4;
    q4.x = p4.x + (c4.x - p4.x);
    q4.y = p4.y + (c4.y - p4.y);
    q4.z = p4.z + (c4.z - p4.z);
    q4.w = p4.w + (c4.w - p4.w);
    float dx = c4.x - p4.x, dy = c4.y - p4.y, dz = c4.z - p4.z, dw = c4.w - p4.w;
    se[tid] = dx * dx + dy * dy + dz * dz + dw * dw;
    __syncthreads();
    if (slot == 0) {
        float t = 0.f;
        #pragma unroll
        for (int j = 0; j < 48; j++) t += se[sl * 48 + j];
        g_epart[s] = t;
    }
    float4* qb = (float4*)out + (long)s * 384 + slot;
    #pragma unroll
    for (int tk = 0; tk < SPAN_; tk++) qb[tk * 48] = q4;
    if (slot < SPAN_) out[IDX_OFF + s * SPAN_ + slot] = (float)idx;
}

// ---------------------------------------------------------------------------
// K4: deterministic loss reduction (R10, unchanged).
// ---------------------------------------------------------------------------
__global__ void __launch_bounds__(256) k4_loss(float* __restrict__ out)
{
    __shared__ double rd[256];
    const int tid = threadIdx.x;
    double a = 0.0;
    for (int i = tid; i < BS_; i += 256) a += (double)g_epart[i];
    rd[tid] = a;
    __syncthreads();
    for (int step = 128; step > 0; step >>= 1) {
        if (tid < step) rd[tid] += rd[tid + step];
        __syncthreads();
    }
    if (tid == 0) {
        float e_mean = (float)(rd[0] / (double)((long)BS_ * DD_));
        float bm = (float)g_bcount / (float)NTOK_;
        float dbm = bm - (1.0f / SPAN_);
        out[LOSS_OFF] = 0.25f * e_mean + 0.01f * dbm * dbm;
    }
}

// ---------------------------------------------------------------------------
extern "C" void kernel_launch(void* const* d_in, const int* in_sizes, int n_in,
                              void* d_out, int out_size)
{
    const float* x  = (const float*)d_in[0];
    const float* cb = (const float*)d_in[1];
    const float* bw = (const float*)d_in[2];
    const float* bb = (const float*)d_in[3];
    float* out = (float*)d_out;
    (void)in_sizes; (void)n_in; (void)out_size;

    cudaFuncSetAttribute(k2_vq, cudaFuncAttributeMaxDynamicSharedMemorySize,
                         K2_DYN);

    k_prep<<<96, 256>>>(cb);
    k1_pool_boundary<<<NTOK_ / 256, 256>>>(x, bw, bb, out + BND_OFF);
    k2_vq<<<GRID2_, NTHR2_, K2_DYN>>>();
    k3_expand<<<BS_ / 4, 192>>>(cb, out);
    k4_loss<<<1, 256>>>(out);
}